// round 13
// baseline (speedup 1.0000x reference)
#include <cuda_runtime.h>
#include <cstdint>

// Problem constants (fixed by the reference)
#define N_CLASSES 50000
#define EMBED_DIM 128
#define N_TOKENS  2048

#define TPB   256                 // threads per block
#define VPT8  8                   // 32-byte (v8) vectors per thread
// total 32B vectors: N_CLASSES*N_TOKENS*4B / 32B = 12,800,000
//   = 6,250 blocks * 256 threads * 8
#define NBLOCKS (N_CLASSES * (N_TOKENS / 8) / (TPB * VPT8))

struct u32x8 { uint4 lo, hi; };

// 256-bit streaming global load (sm_100a: LDG.E.256). Address must be
// 32B-aligned: guaranteed (cudaMalloc alignment + 32B-strided indexing).
__device__ __forceinline__ u32x8 ldg256(const void* __restrict__ p)
{
    u32x8 r;
    asm volatile(
        "ld.global.nc.v8.u32 {%0,%1,%2,%3,%4,%5,%6,%7}, [%8];"
        : "=r"(r.lo.x), "=r"(r.lo.y), "=r"(r.lo.z), "=r"(r.lo.w),
          "=r"(r.hi.x), "=r"(r.hi.y), "=r"(r.hi.z), "=r"(r.hi.w)
        : "l"(p));
    return r;
}

// ---------------------------------------------------------------------------
// Solo fallback gather (used only if one thread finds >4 tokens -- practically
// never, but keeps correctness unconditional).
// ---------------------------------------------------------------------------
__device__ __forceinline__ void gather_token_solo(
    const float* __restrict__ lookup, float* __restrict__ out, int c, int n)
{
    const float* __restrict__ src = lookup + c;
    float4* __restrict__ dst = reinterpret_cast<float4*>(out + n * EMBED_DIM);
    #pragma unroll 8
    for (int j = 0; j < EMBED_DIM / 4; ++j) {
        float4 r;
        r.x = src[(size_t)(4 * j + 0) * N_CLASSES];
        r.y = src[(size_t)(4 * j + 1) * N_CLASSES];
        r.z = src[(size_t)(4 * j + 2) * N_CLASSES];
        r.w = src[(size_t)(4 * j + 3) * N_CLASSES];
        dst[j] = r;
    }
}

// Record the hits inside one nonzero uint4 (float4 index i).
__device__ __forceinline__ void record_hits(
    const uint4& q, unsigned int i, int& cnt, unsigned int (&enc)[4],
    const float* __restrict__ lookup, float* __restrict__ out)
{
    const unsigned int c  = i >> 9;            // class row (512 f4/row)
    const unsigned int nb = (i & 511u) << 2;   // token col base
    #pragma unroll
    for (int t = 0; t < 4; ++t) {
        const unsigned int elem =
            (t == 0) ? q.x : (t == 1) ? q.y : (t == 2) ? q.z : q.w;
        if (elem != 0u) {
            if (cnt < 4) enc[cnt++] = (c << 11) | (nb + t);
            else gather_token_solo(lookup, out, (int)c, (int)(nb + t));
        }
    }
}

// ---------------------------------------------------------------------------
// Fused scan + warp-cooperative gather over the dense one-hot matrix
// [N_CLASSES, N_TOKENS] (row-major fp32). Non-persistent: 6,250 short-lived
// CTAs, HW backfill. Each thread front-batches 8 x 256-bit loads (blockDim-
// strided in 32B units, coalesced) -- same bytes/addresses/registers as the
// proven 16 x LDG.128 version but half the LDG instructions and half the
// L1tex wavefront-queue entries. Finder threads encode hits as (c<<11)|n; a
// warp ballot lets all 32 lanes gather each hit token cooperatively (lane
// handles dims 4*lane..+3; coalesced 512 B output store). Integer compare vs
// 0 is exact: one_hot yields only 0.0f (0x00000000) and 1.0f, never -0.0.
// ---------------------------------------------------------------------------
__global__ void __launch_bounds__(TPB) onehot_embed_fused_kernel(
    const uint4* __restrict__ types_v4,
    const float* __restrict__ lookup,
    float*       __restrict__ out)
{
    // Index in 32-byte (v8) units.
    const unsigned int base8 = blockIdx.x * (TPB * VPT8) + threadIdx.x;

    u32x8 v[VPT8];
    #pragma unroll
    for (int u = 0; u < VPT8; ++u)
        v[u] = ldg256(&types_v4[(size_t)(base8 + u * TPB) * 2]);

    unsigned int any = 0;
    #pragma unroll
    for (int u = 0; u < VPT8; ++u)
        any |= v[u].lo.x | v[u].lo.y | v[u].lo.z | v[u].lo.w
             | v[u].hi.x | v[u].hi.y | v[u].hi.z | v[u].hi.w;

    // Encode up to 4 hits per thread as (class << 11) | token  (n < 2048).
    int cnt = 0;
    unsigned int enc[4];
    if (any != 0u) {                              // rare: ~2048 / 1.6M threads
        #pragma unroll
        for (int u = 0; u < VPT8; ++u) {
            const unsigned int i = (base8 + u * TPB) * 2;   // float4 index
            if ((v[u].lo.x | v[u].lo.y | v[u].lo.z | v[u].lo.w) != 0u)
                record_hits(v[u].lo, i,     cnt, enc, lookup, out);
            if ((v[u].hi.x | v[u].hi.y | v[u].hi.z | v[u].hi.w) != 0u)
                record_hits(v[u].hi, i + 1, cnt, enc, lookup, out);
        }
    }

    // Warp-cooperative gather of all hits found in this warp.
    const unsigned int lane = threadIdx.x & 31u;
    unsigned int hitmask = __ballot_sync(0xffffffffu, cnt > 0);
    while (hitmask) {
        const int leader = __ffs(hitmask) - 1;
        hitmask &= hitmask - 1;
        const int lcnt = __shfl_sync(0xffffffffu, cnt, leader);
        #pragma unroll
        for (int k = 0; k < 4; ++k) {
            if (k < lcnt) {
                const unsigned int e = __shfl_sync(0xffffffffu, enc[k], leader);
                const int c = (int)(e >> 11);
                const int n = (int)(e & 2047u);
                const float* __restrict__ src = lookup + c;
                float4 r;
                r.x = src[(size_t)(4 * lane + 0) * N_CLASSES];
                r.y = src[(size_t)(4 * lane + 1) * N_CLASSES];
                r.z = src[(size_t)(4 * lane + 2) * N_CLASSES];
                r.w = src[(size_t)(4 * lane + 3) * N_CLASSES];
                reinterpret_cast<float4*>(out + n * EMBED_DIM)[lane] = r;
            }
        }
    }
}

extern "C" void kernel_launch(void* const* d_in, const int* in_sizes, int n_in,
                              void* d_out, int out_size)
{
    // Resolve inputs by size: types has 102,400,000 elems, lookup 6,400,000.
    const float* types  = (const float*)d_in[0];
    const float* lookup = (const float*)d_in[1];
    if (n_in >= 2 && in_sizes[0] == EMBED_DIM * N_CLASSES &&
        in_sizes[1] == N_CLASSES * N_TOKENS) {
        const float* t = types; types = lookup; lookup = t;
    }

    onehot_embed_fused_kernel<<<NBLOCKS, TPB>>>(
        (const uint4*)types, lookup, (float*)d_out);
}

// round 14
// speedup vs baseline: 1.0853x; 1.0853x over previous
#include <cuda_runtime.h>
#include <cstdint>

// Problem constants (fixed by the reference)
#define N_CLASSES 50000
#define EMBED_DIM 128
#define N_TOKENS  2048

#define TPB   256                 // threads per block
#define VPT   16                  // float4 vectors per thread
// total float4: N_CLASSES*N_TOKENS/4 = 25,600,000 = 6,250 blocks * 256 * 16
#define NBLOCKS (N_CLASSES * (N_TOKENS / 4) / (TPB * VPT))

// ---------------------------------------------------------------------------
// Solo fallback gather (used only if one thread finds >4 tokens -- practically
// never, but keeps correctness unconditional).
// ---------------------------------------------------------------------------
__device__ __forceinline__ void gather_token_solo(
    const float* __restrict__ lookup, float* __restrict__ out, int c, int n)
{
    const float* __restrict__ src = lookup + c;
    float4* __restrict__ dst = reinterpret_cast<float4*>(out + n * EMBED_DIM);
    #pragma unroll 8
    for (int j = 0; j < EMBED_DIM / 4; ++j) {
        float4 r;
        r.x = src[(size_t)(4 * j + 0) * N_CLASSES];
        r.y = src[(size_t)(4 * j + 1) * N_CLASSES];
        r.z = src[(size_t)(4 * j + 2) * N_CLASSES];
        r.w = src[(size_t)(4 * j + 3) * N_CLASSES];
        dst[j] = r;
    }
}

// ---------------------------------------------------------------------------
// Fused scan + warp-cooperative gather over the dense one-hot matrix
// [N_CLASSES, N_TOKENS] (row-major fp32). Non-persistent: 6,250 short-lived
// CTAs, HW backfill (proven fastest launch shape). Each thread front-batches
// 16 float4 loads (blockDim-strided, coalesced, evict-first). Finder threads
// encode hits as (c<<11)|n; a warp ballot then lets all 32 lanes gather each
// hit token cooperatively: lane handles dims 4*lane..+3 (one DRAM round-trip
// instead of four, coalesced 512 B output store). Integer compare vs 0 is
// exact: one_hot yields only 0.0f (0x00000000) and 1.0f, never -0.0.
// ---------------------------------------------------------------------------
__global__ void __launch_bounds__(TPB) onehot_embed_fused_kernel(
    const uint4* __restrict__ types_v4,
    const float* __restrict__ lookup,
    float*       __restrict__ out)
{
    const unsigned int base = blockIdx.x * (TPB * VPT) + threadIdx.x;

    uint4 v[VPT];
    #pragma unroll
    for (int u = 0; u < VPT; ++u)
        v[u] = __ldcs(&types_v4[base + u * TPB]);

    unsigned int any = 0;
    #pragma unroll
    for (int u = 0; u < VPT; ++u)
        any |= v[u].x | v[u].y | v[u].z | v[u].w;

    // Encode up to 4 hits per thread as (class << 11) | token  (n < 2048).
    int cnt = 0;
    unsigned int enc[4];
    if (any != 0u) {                              // rare: ~2048 / 1.6M threads
        #pragma unroll
        for (int u = 0; u < VPT; ++u) {
            if ((v[u].x | v[u].y | v[u].z | v[u].w) != 0u) {
                const unsigned int i = base + u * TPB;   // float4 index
                const unsigned int c = i >> 9;           // class row (512 f4/row)
                const unsigned int nb = (i & 511u) << 2; // token col base
                #pragma unroll
                for (int q = 0; q < 4; ++q) {
                    const unsigned int elem =
                        (q == 0) ? v[u].x : (q == 1) ? v[u].y :
                        (q == 2) ? v[u].z : v[u].w;
                    if (elem != 0u) {
                        if (cnt < 4) enc[cnt++] = (c << 11) | (nb + q);
                        else gather_token_solo(lookup, out, (int)c, (int)(nb + q));
                    }
                }
            }
        }
    }

    // Warp-cooperative gather of all hits found in this warp.
    const unsigned int lane = threadIdx.x & 31u;
    unsigned int hitmask = __ballot_sync(0xffffffffu, cnt > 0);
    while (hitmask) {
        const int leader = __ffs(hitmask) - 1;
        hitmask &= hitmask - 1;
        const int lcnt = __shfl_sync(0xffffffffu, cnt, leader);
        #pragma unroll
        for (int k = 0; k < 4; ++k) {
            if (k < lcnt) {
                const unsigned int e = __shfl_sync(0xffffffffu, enc[k], leader);
                const int c = (int)(e >> 11);
                const int n = (int)(e & 2047u);
                const float* __restrict__ src = lookup + c;
                float4 r;
                r.x = src[(size_t)(4 * lane + 0) * N_CLASSES];
                r.y = src[(size_t)(4 * lane + 1) * N_CLASSES];
                r.z = src[(size_t)(4 * lane + 2) * N_CLASSES];
                r.w = src[(size_t)(4 * lane + 3) * N_CLASSES];
                reinterpret_cast<float4*>(out + n * EMBED_DIM)[lane] = r;
            }
        }
    }
}

extern "C" void kernel_launch(void* const* d_in, const int* in_sizes, int n_in,
                              void* d_out, int out_size)
{
    // Resolve inputs by size: types has 102,400,000 elems, lookup 6,400,000.
    const float* types  = (const float*)d_in[0];
    const float* lookup = (const float*)d_in[1];
    if (n_in >= 2 && in_sizes[0] == EMBED_DIM * N_CLASSES &&
        in_sizes[1] == N_CLASSES * N_TOKENS) {
        const float* t = types; types = lookup; lookup = t;
    }

    onehot_embed_fused_kernel<<<NBLOCKS, TPB>>>(
        (const uint4*)types, lookup, (float*)d_out);
}

// round 16
// speedup vs baseline: 1.0932x; 1.0072x over previous
#include <cuda_runtime.h>
#include <cstdint>

// Problem constants (fixed by the reference)
#define N_CLASSES 50000
#define EMBED_DIM 128
#define N_TOKENS  2048

#define TPB   128                 // threads per block (granularity sweep)
#define VPT   16                  // float4 vectors per thread
// total float4: N_CLASSES*N_TOKENS/4 = 25,600,000 = 12,500 blocks * 128 * 16
#define NBLOCKS (N_CLASSES * (N_TOKENS / 4) / (TPB * VPT))

// ---------------------------------------------------------------------------
// Solo fallback gather (used only if one thread finds >4 tokens -- practically
// never, but keeps correctness unconditional).
// ---------------------------------------------------------------------------
__device__ __forceinline__ void gather_token_solo(
    const float* __restrict__ lookup, float* __restrict__ out, int c, int n)
{
    const float* __restrict__ src = lookup + c;
    float4* __restrict__ dst = reinterpret_cast<float4*>(out + n * EMBED_DIM);
    #pragma unroll 8
    for (int j = 0; j < EMBED_DIM / 4; ++j) {
        float4 r;
        r.x = src[(size_t)(4 * j + 0) * N_CLASSES];
        r.y = src[(size_t)(4 * j + 1) * N_CLASSES];
        r.z = src[(size_t)(4 * j + 2) * N_CLASSES];
        r.w = src[(size_t)(4 * j + 3) * N_CLASSES];
        dst[j] = r;
    }
}

// ---------------------------------------------------------------------------
// Fused scan + warp-cooperative gather over the dense one-hot matrix
// [N_CLASSES, N_TOKENS] (row-major fp32). Non-persistent short-lived CTAs,
// HW backfill. Each thread front-batches 16 float4 loads (blockDim-strided,
// coalesced, evict-first). Finder threads encode hits as (c<<11)|n; a warp
// ballot then lets all 32 lanes gather each hit token cooperatively: lane
// handles dims 4*lane..+3 (one DRAM round-trip instead of four, coalesced
// 512 B output store). Integer compare vs 0 is exact: one_hot yields only
// 0.0f (0x00000000) and 1.0f, never -0.0.
// ---------------------------------------------------------------------------
__global__ void __launch_bounds__(TPB) onehot_embed_fused_kernel(
    const uint4* __restrict__ types_v4,
    const float* __restrict__ lookup,
    float*       __restrict__ out)
{
    const unsigned int base = blockIdx.x * (TPB * VPT) + threadIdx.x;

    uint4 v[VPT];
    #pragma unroll
    for (int u = 0; u < VPT; ++u)
        v[u] = __ldcs(&types_v4[base + u * TPB]);

    unsigned int any = 0;
    #pragma unroll
    for (int u = 0; u < VPT; ++u)
        any |= v[u].x | v[u].y | v[u].z | v[u].w;

    // Encode up to 4 hits per thread as (class << 11) | token  (n < 2048).
    int cnt = 0;
    unsigned int enc[4];
    if (any != 0u) {                              // rare: ~2048 / 1.6M threads
        #pragma unroll
        for (int u = 0; u < VPT; ++u) {
            if ((v[u].x | v[u].y | v[u].z | v[u].w) != 0u) {
                const unsigned int i = base + u * TPB;   // float4 index
                const unsigned int c = i >> 9;           // class row (512 f4/row)
                const unsigned int nb = (i & 511u) << 2; // token col base
                #pragma unroll
                for (int q = 0; q < 4; ++q) {
                    const unsigned int elem =
                        (q == 0) ? v[u].x : (q == 1) ? v[u].y :
                        (q == 2) ? v[u].z : v[u].w;
                    if (elem != 0u) {
                        if (cnt < 4) enc[cnt++] = (c << 11) | (nb + q);
                        else gather_token_solo(lookup, out, (int)c, (int)(nb + q));
                    }
                }
            }
        }
    }

    // Warp-cooperative gather of all hits found in this warp.
    const unsigned int lane = threadIdx.x & 31u;
    unsigned int hitmask = __ballot_sync(0xffffffffu, cnt > 0);
    while (hitmask) {
        const int leader = __ffs(hitmask) - 1;
        hitmask &= hitmask - 1;
        const int lcnt = __shfl_sync(0xffffffffu, cnt, leader);
        #pragma unroll
        for (int k = 0; k < 4; ++k) {
            if (k < lcnt) {
                const unsigned int e = __shfl_sync(0xffffffffu, enc[k], leader);
                const int c = (int)(e >> 11);
                const int n = (int)(e & 2047u);
                const float* __restrict__ src = lookup + c;
                float4 r;
                r.x = src[(size_t)(4 * lane + 0) * N_CLASSES];
                r.y = src[(size_t)(4 * lane + 1) * N_CLASSES];
                r.z = src[(size_t)(4 * lane + 2) * N_CLASSES];
                r.w = src[(size_t)(4 * lane + 3) * N_CLASSES];
                reinterpret_cast<float4*>(out + n * EMBED_DIM)[lane] = r;
            }
        }
    }
}

extern "C" void kernel_launch(void* const* d_in, const int* in_sizes, int n_in,
                              void* d_out, int out_size)
{
    // Resolve inputs by size: types has 102,400,000 elems, lookup 6,400,000.
    const float* types  = (const float*)d_in[0];
    const float* lookup = (const float*)d_in[1];
    if (n_in >= 2 && in_sizes[0] == EMBED_DIM * N_CLASSES &&
        in_sizes[1] == N_CLASSES * N_TOKENS) {
        const float* t = types; types = lookup; lookup = t;
    }

    onehot_embed_fused_kernel<<<NBLOCKS, TPB>>>(
        (const uint4*)types, lookup, (float*)d_out);
}